// round 3
// baseline (speedup 1.0000x reference)
#include <cuda_runtime.h>

// Flow1: reparam + 4 affine-coupling half-layers + densities.
// B=262144 rows, Z=128, ZH=64, HS=50 (padded to 64), NF=2 -> 4 couplings.
// Output: [ z (B*128) | logpz (B) | logqz (B) ] fp32.
//
// CTA processes R=64 rows. All activations in SMEM, transposed [k][row] with
// pitch 68 floats. Each GEMM is 64x64x64; each thread owns a 4x4 output tile
// (16x16 thread grid), register-blocked with float4 LDS.

#define ZZ   128
#define ZH   64
#define HS   50
#define NC   4
#define TPB  256
#define RR   64        // rows per CTA
#define PIT  68        // transposed-tile pitch (floats), mult of 4

// shared layout (float offsets)
#define OFF_Z1   0
#define OFF_Z2   (OFF_Z1 + 64*PIT)      // 4352
#define OFF_H    (OFF_Z2 + 64*PIT)      // 8704
#define OFF_W0   (OFF_H  + 64*PIT)      // 13056
#define OFF_W1   (OFF_W0 + 64*PIT)      // 17408
#define OFF_W2   (OFF_W1 + 64*PIT)      // 21760
#define OFF_B0   (OFF_W2 + 64*PIT)      // 26112
#define OFF_B1   (OFF_B0 + 64)
#define OFF_B2   (OFF_B1 + 64)
#define OFF_Q0   (OFF_B2 + 64)
#define SMEM_FLOATS (OFF_Q0 + 64)       // 26368
#define SMEM_BYTES  (SMEM_FLOATS * 4)   // 105472
// reduction scratch aliases OFF_H after last coupling:
#define OFF_SS   OFF_H                   // 16*64 floats
#define OFF_LD   (OFF_H + 1024)          // 16*64 floats

__device__ __forceinline__ float tanh_fast(float x) {
    float r;
    asm("tanh.approx.f32 %0, %1;" : "=f"(r) : "f"(x));
    return r;
}

__global__ void __launch_bounds__(TPB, 2)
flow_kernel(const float* __restrict__ mean,  const float* __restrict__ logvar,
            const float* __restrict__ eps,
            const float* __restrict__ W_in,  const float* __restrict__ b_in,
            const float* __restrict__ W_mu,  const float* __restrict__ b_mu,
            const float* __restrict__ W_sig, const float* __restrict__ b_sig,
            float* __restrict__ out, int Brows)
{
    extern __shared__ float sm[];
    float* sZ1 = sm + OFF_Z1;
    float* sZ2 = sm + OFF_Z2;
    float* sH  = sm + OFF_H;
    float* sW0 = sm + OFF_W0;
    float* sW1 = sm + OFF_W1;
    float* sW2 = sm + OFF_W2;
    float* sB0 = sm + OFF_B0;
    float* sB1 = sm + OFF_B1;
    float* sB2 = sm + OFF_B2;
    float* sQ0 = sm + OFF_Q0;

    const int tid = threadIdx.x;
    const int wl  = tid & 31;          // lane
    const int wd  = tid >> 5;          // warp
    const int tr  = tid & 15;          // tile row group
    const int tc  = tid >> 4;          // tile col group
    const int r0  = tr * 4;
    const int c0  = tc * 4;
    const int rowBase = blockIdx.x * RR;

    // ---------------- reparam load phase ----------------
    // thread t handles quads f = t + 256*i : row = wd + 8*i, quad = wl (k = 4*wl)
#pragma unroll
    for (int i = 0; i < 8; i++) {
        int row  = wd + 8 * i;
        int gRow = rowBase + row;
        const float4 mv = reinterpret_cast<const float4*>(mean  )[(size_t)gRow * 32 + wl];
        const float4 lv = reinterpret_cast<const float4*>(logvar)[(size_t)gRow * 32 + wl];
        const float4 ev = reinterpret_cast<const float4*>(eps   )[(size_t)gRow * 32 + wl];
        float z[4];
        z[0] = fmaf(ev.x, __expf(0.5f * lv.x), mv.x);
        z[1] = fmaf(ev.y, __expf(0.5f * lv.y), mv.y);
        z[2] = fmaf(ev.z, __expf(0.5f * lv.z), mv.z);
        z[3] = fmaf(ev.w, __expf(0.5f * lv.w), mv.w);
        float part = lv.x + lv.y + lv.z + lv.w;
        part = fmaf(ev.x, ev.x, part);
        part = fmaf(ev.y, ev.y, part);
        part = fmaf(ev.z, ev.z, part);
        part = fmaf(ev.w, ev.w, part);
        int k = 4 * wl;
        if (k < ZH) {
#pragma unroll
            for (int d = 0; d < 4; d++) sZ1[(k + d) * PIT + row] = z[d];
        } else {
#pragma unroll
            for (int d = 0; d < 4; d++) sZ2[(k - ZH + d) * PIT + row] = z[d];
        }
        // per-row reduction: all 32 lanes of this warp share `row`
#pragma unroll
        for (int s = 16; s > 0; s >>= 1)
            part += __shfl_xor_sync(0xffffffffu, part, s);
        if (wl == 0) sQ0[row] = -0.5f * part;
    }
    __syncthreads();

    float ld_part[4] = {0.f, 0.f, 0.f, 0.f};   // sum log(sig) for my 4 rows
    float ss_part[4] = {0.f, 0.f, 0.f, 0.f};   // sum z^2 (final) for my 4 rows

    // ---------------- couplings ----------------
#pragma unroll 1
    for (int c = 0; c < NC; c++) {
        // ---- stage this coupling's weights (transposed, zero-padded) ----
        // W0: raw [HS][ZH] -> sW0[k*PIT + j], rows j>=HS zero
        for (int idx = tid; idx < 64 * 64; idx += TPB) {
            int j = idx >> 6, k = idx & 63;
            float v = (idx < HS * ZH) ? W_in[c * HS * ZH + idx] : 0.0f;
            sW0[k * PIT + j] = v;
        }
        // W1/W2: raw [ZH][HS] -> sW[j*PIT + i], rows j>=HS zero
        for (int idx = tid; idx < ZH * HS; idx += TPB) {
            int io = idx / HS, j = idx - io * HS;
            sW1[j * PIT + io] = W_mu [c * ZH * HS + idx];
            sW2[j * PIT + io] = W_sig[c * ZH * HS + idx];
        }
        for (int idx = tid; idx < (64 - HS) * 64; idx += TPB) {
            int j = HS + (idx >> 6), i = idx & 63;
            sW1[j * PIT + i] = 0.0f;
            sW2[j * PIT + i] = 0.0f;
        }
        if (tid < 64) {
            sB0[tid] = (tid < HS) ? b_in[c * HS + tid] : 0.0f;
            sB1[tid] = b_mu [c * ZH + tid];
            sB2[tid] = b_sig[c * ZH + tid];
        }
        __syncthreads();

        const float* sZa = (c & 1) ? sZ2 : sZ1;   // coupling input
        float*       sZu = (c & 1) ? sZ1 : sZ2;   // coupling target

        // ---- GEMM1: H = tanh(Za @ W0^T + b0), 64x64x64 ----
        {
            float acc[4][4] = {};
#pragma unroll 8
            for (int k = 0; k < 64; k++) {
                float4 a = *reinterpret_cast<const float4*>(&sZa[k * PIT + r0]);
                float4 b = *reinterpret_cast<const float4*>(&sW0[k * PIT + c0]);
                const float av[4] = {a.x, a.y, a.z, a.w};
                const float bv[4] = {b.x, b.y, b.z, b.w};
#pragma unroll
                for (int i = 0; i < 4; i++)
#pragma unroll
                    for (int j = 0; j < 4; j++)
                        acc[i][j] = fmaf(av[i], bv[j], acc[i][j]);
            }
#pragma unroll
            for (int j = 0; j < 4; j++) {
                float bb = sB0[c0 + j];
#pragma unroll
                for (int i = 0; i < 4; i++)
                    sH[(c0 + j) * PIT + (r0 + i)] = tanh_fast(acc[i][j] + bb);
            }
        }
        __syncthreads();

        // ---- GEMM2: mu/sig heads + z update + logdet ----
        {
            float am[4][4] = {};
            float as[4][4] = {};
#pragma unroll 4
            for (int k = 0; k < 64; k++) {
                float4 a  = *reinterpret_cast<const float4*>(&sH [k * PIT + r0]);
                float4 b1 = *reinterpret_cast<const float4*>(&sW1[k * PIT + c0]);
                float4 b2 = *reinterpret_cast<const float4*>(&sW2[k * PIT + c0]);
                const float av[4]  = {a.x, a.y, a.z, a.w};
                const float b1v[4] = {b1.x, b1.y, b1.z, b1.w};
                const float b2v[4] = {b2.x, b2.y, b2.z, b2.w};
#pragma unroll
                for (int i = 0; i < 4; i++)
#pragma unroll
                    for (int j = 0; j < 4; j++) {
                        am[i][j] = fmaf(av[i], b1v[j], am[i][j]);
                        as[i][j] = fmaf(av[i], b2v[j], as[i][j]);
                    }
            }
            bool takeSS = (c >= 2);   // c==2: z2 final, c==3: z1 final
#pragma unroll
            for (int j = 0; j < 4; j++) {
                float bm = sB1[c0 + j];
                float bs = sB2[c0 + j];
#pragma unroll
                for (int i = 0; i < 4; i++) {
                    float m  = am[i][j] + bm;
                    float sg = as[i][j] + bs;
                    float ex  = __expf(-sg);
                    float sig = __fdividef(1.0f, 1.0f + ex);
                    float zo = sZu[(c0 + j) * PIT + (r0 + i)];
                    float zn = fmaf(zo, sig, m);
                    sZu[(c0 + j) * PIT + (r0 + i)] = zn;
                    ld_part[i] -= __logf(1.0f + ex);           // += log(sig)
                    if (takeSS) ss_part[i] = fmaf(zn, zn, ss_part[i]);
                }
            }
        }
        __syncthreads();
    }

    // ---------------- write z ----------------
#pragma unroll
    for (int i = 0; i < 8; i++) {
        int row  = wd + 8 * i;
        int gRow = rowBase + row;
        int k = 4 * wl;
        float4 v;
        if (k < ZH) {
            v.x = sZ1[(k + 0) * PIT + row];
            v.y = sZ1[(k + 1) * PIT + row];
            v.z = sZ1[(k + 2) * PIT + row];
            v.w = sZ1[(k + 3) * PIT + row];
        } else {
            v.x = sZ2[(k - ZH + 0) * PIT + row];
            v.y = sZ2[(k - ZH + 1) * PIT + row];
            v.z = sZ2[(k - ZH + 2) * PIT + row];
            v.w = sZ2[(k - ZH + 3) * PIT + row];
        }
        reinterpret_cast<float4*>(out)[(size_t)gRow * 32 + wl] = v;
    }

    // ---------------- densities: reduce 16 partials per row ----------------
    // sH is dead now; alias reduction scratch onto it.
    float* sSS = sm + OFF_SS;
    float* sLD = sm + OFF_LD;
#pragma unroll
    for (int i = 0; i < 4; i++) {
        sSS[tc * 64 + (r0 + i)] = ss_part[i];
        sLD[tc * 64 + (r0 + i)] = ld_part[i];
    }
    __syncthreads();
    if (tid < 64) {
        float ssum = 0.f, lsum = 0.f;
#pragma unroll
        for (int t = 0; t < 16; t++) {
            ssum += sSS[t * 64 + tid];
            lsum += sLD[t * 64 + tid];
        }
        int gRow = rowBase + tid;
        size_t base = (size_t)Brows * ZZ;
        out[base + gRow]         = -0.5f * ssum;
        out[base + Brows + gRow] = sQ0[tid] - lsum;
    }
}

extern "C" void kernel_launch(void* const* d_in, const int* in_sizes, int n_in,
                              void* d_out, int out_size)
{
    const float* mean   = (const float*)d_in[0];
    const float* logvar = (const float*)d_in[1];
    const float* eps    = (const float*)d_in[2];
    const float* W_in   = (const float*)d_in[3];
    const float* b_in   = (const float*)d_in[4];
    const float* W_mu   = (const float*)d_in[5];
    const float* b_mu   = (const float*)d_in[6];
    const float* W_sig  = (const float*)d_in[7];
    const float* b_sig  = (const float*)d_in[8];
    float* out = (float*)d_out;

    int Brows = in_sizes[0] / ZZ;

    static int attr_set = 0;
    if (!attr_set) {
        cudaFuncSetAttribute(flow_kernel, cudaFuncAttributeMaxDynamicSharedMemorySize, SMEM_BYTES);
        attr_set = 1;
    }

    int grid = Brows / RR;
    flow_kernel<<<grid, TPB, SMEM_BYTES>>>(mean, logvar, eps,
                                           W_in, b_in, W_mu, b_mu, W_sig, b_sig,
                                           out, Brows);
}

// round 5
// speedup vs baseline: 1.2729x; 1.2729x over previous
#include <cuda_runtime.h>
#include <cstdint>

// Flow1 via warp-level mma.sync (m16n8k8 tf32) with 3xTF32 compensation.
// B=262144 rows, Z=128, ZH=64, HS=50 (padded 56), 4 couplings.
// Out: [ z (B*128) | logpz (B) | logqz (B) ] fp32.
//
// CTA = 64 rows, 256 thr = 8 warps = 4 m-groups x 2 n-halves.
// Activations fp32 in SMEM, pitch 68 floats (272B: float4-aligned, and
// fragment loads hit all 32 banks: addr%32 = 4*gid + tig).

#define ZZ 128
#define ZH 64
#define HS 50
#define NH 56      // padded HS (7 k/n tiles)
#define NC 4
#define TPB 256
#define MR 64      // rows per CTA
#define PZ 68      // pitch (floats) for all 2D smem arrays

// smem float offsets
#define OZ1 0
#define OZ2 4352            // 64*68
#define OH  8704
#define OW0 13056           // 56*68 = 3808
#define OW1 16864           // 64*68
#define OW2 21216
#define OB0 25568           // 64
#define OB1 25632
#define OB2 25696
#define OQ0 25760           // 64
#define OLD 25824           // 2*64
#define OSS 25952           // 2*64
#define SMEM_FLOATS 26080
#define SMEM_BYTES  (SMEM_FLOATS * 4)   // 104320

__device__ __forceinline__ float tanh_fast(float x) {
    float r;
    asm("tanh.approx.f32 %0, %1;" : "=f"(r) : "f"(x));
    return r;
}
__device__ __forceinline__ void split_tf32(float x, uint32_t& hi, uint32_t& lo) {
    asm("cvt.rna.tf32.f32 %0, %1;" : "=r"(hi) : "f"(x));
    float r = x - __uint_as_float(hi);
    asm("cvt.rna.tf32.f32 %0, %1;" : "=r"(lo) : "f"(r));
}
__device__ __forceinline__ void mma8(float (&d)[4], const uint32_t* a,
                                     uint32_t b0, uint32_t b1) {
    asm volatile(
        "mma.sync.aligned.m16n8k8.row.col.f32.tf32.tf32.f32 "
        "{%0,%1,%2,%3}, {%4,%5,%6,%7}, {%8,%9}, {%0,%1,%2,%3};"
        : "+f"(d[0]), "+f"(d[1]), "+f"(d[2]), "+f"(d[3])
        : "r"(a[0]), "r"(a[1]), "r"(a[2]), "r"(a[3]), "r"(b0), "r"(b1));
}

__global__ void __launch_bounds__(TPB, 2)
flow_kernel(const float* __restrict__ mean,  const float* __restrict__ logvar,
            const float* __restrict__ eps,
            const float* __restrict__ W_in,  const float* __restrict__ b_in,
            const float* __restrict__ W_mu,  const float* __restrict__ b_mu,
            const float* __restrict__ W_sig, const float* __restrict__ b_sig,
            float* __restrict__ out, int Brows)
{
    extern __shared__ float sm[];
    float* sZ1 = sm + OZ1;
    float* sZ2 = sm + OZ2;
    float* sH  = sm + OH;
    float* sW0 = sm + OW0;
    float* sW1 = sm + OW1;
    float* sW2 = sm + OW2;
    float* sB0 = sm + OB0;
    float* sB1 = sm + OB1;
    float* sB2 = sm + OB2;
    float* sQ0 = sm + OQ0;
    float* sLD = sm + OLD;
    float* sSS = sm + OSS;

    const int tid  = threadIdx.x;
    const int lane = tid & 31;
    const int wid  = tid >> 5;
    const int wm   = wid & 3;          // m-group: rows 16*wm .. +15
    const int wn   = wid >> 2;         // n-half
    const int gid  = lane >> 2;        // fragment row group 0..7
    const int tig  = lane & 3;         // thread-in-group
    const int m0   = 16 * wm;
    const int r0   = m0 + gid;         // fragment row A
    const int r1   = r0 + 8;           // fragment row B
    const int rowBase = blockIdx.x * MR;

    // ================= reparam =================
    {
        const int rrow = tid >> 2, p = tid & 3;
        float part = 0.0f;
#pragma unroll
        for (int j = 0; j < 8; j++) {
            int q = p + 4 * j;                     // float4 col index 0..31
            size_t g = (size_t)(rowBase + rrow) * 32 + q;
            float4 mv = ((const float4*)mean  )[g];
            float4 lv = ((const float4*)logvar)[g];
            float4 ev = ((const float4*)eps   )[g];
            float4 z4;
            z4.x = fmaf(ev.x, __expf(0.5f * lv.x), mv.x);
            z4.y = fmaf(ev.y, __expf(0.5f * lv.y), mv.y);
            z4.z = fmaf(ev.z, __expf(0.5f * lv.z), mv.z);
            z4.w = fmaf(ev.w, __expf(0.5f * lv.w), mv.w);
            part += lv.x + lv.y + lv.z + lv.w;
            part = fmaf(ev.x, ev.x, part);
            part = fmaf(ev.y, ev.y, part);
            part = fmaf(ev.z, ev.z, part);
            part = fmaf(ev.w, ev.w, part);
            if (q < 16)
                *(float4*)&sZ1[rrow * PZ + 4 * q] = z4;
            else
                *(float4*)&sZ2[rrow * PZ + 4 * (q - 16)] = z4;
        }
        part += __shfl_xor_sync(0xffffffffu, part, 1);
        part += __shfl_xor_sync(0xffffffffu, part, 2);
        if (p == 0) sQ0[rrow] = -0.5f * part;
    }

    float ldp0 = 0.f, ldp1 = 0.f, ssp0 = 0.f, ssp1 = 0.f;

    // ================= couplings =================
#pragma unroll 1
    for (int cc = 0; cc < NC; cc++) {
        // ---- stage weights (zero-padded) ----
        for (int idx = tid; idx < NH * ZH; idx += TPB) {        // 3584
            int n = idx >> 6, k = idx & 63;
            sW0[n * PZ + k] = (n < HS) ? W_in[cc * HS * ZH + n * ZH + k] : 0.0f;
        }
        for (int idx = tid; idx < ZH * NH; idx += TPB) {        // 3584
            int n = idx / NH, k = idx - n * NH;
            float vm = 0.f, vs = 0.f;
            if (k < HS) {
                vm = W_mu [cc * ZH * HS + n * HS + k];
                vs = W_sig[cc * ZH * HS + n * HS + k];
            }
            sW1[n * PZ + k] = vm;
            sW2[n * PZ + k] = vs;
        }
        if (tid < 64) {
            sB0[tid] = (tid < HS) ? b_in[cc * HS + tid] : 0.0f;
            sB1[tid] = b_mu [cc * ZH + tid];
            sB2[tid] = b_sig[cc * ZH + tid];
        }
        __syncthreads();

        const float* sZa = (cc & 1) ? sZ2 : sZ1;   // input half
        float*       sZu = (cc & 1) ? sZ1 : sZ2;   // updated half

        // ---- GEMM1: H = tanh(Za @ W0^T + b0); N=56 (split 4/3) ----
        {
            const int NT1 = wn ? 3 : 4;
            float acc[4][4] = {};
#pragma unroll
            for (int kt = 0; kt < 8; kt++) {
                uint32_t ah[4], al[4];
                split_tf32(sZa[r0 * PZ + tig +     8 * kt], ah[0], al[0]);
                split_tf32(sZa[r1 * PZ + tig +     8 * kt], ah[1], al[1]);
                split_tf32(sZa[r0 * PZ + tig + 4 + 8 * kt], ah[2], al[2]);
                split_tf32(sZa[r1 * PZ + tig + 4 + 8 * kt], ah[3], al[3]);
#pragma unroll
                for (int nn = 0; nn < 4; nn++) {
                    if (nn >= NT1) break;
                    int ntg = wn * 4 + nn;
                    uint32_t bh0, bl0, bh1, bl1;
                    split_tf32(sW0[(8 * ntg + gid) * PZ + tig +     8 * kt], bh0, bl0);
                    split_tf32(sW0[(8 * ntg + gid) * PZ + tig + 4 + 8 * kt], bh1, bl1);
                    mma8(acc[nn], ah, bh0, bh1);
                    mma8(acc[nn], ah, bl0, bl1);
                    mma8(acc[nn], al, bh0, bh1);
                }
            }
#pragma unroll
            for (int nn = 0; nn < 4; nn++) {
                if (nn >= NT1) break;
                int col = 8 * (wn * 4 + nn) + 2 * tig;
                float bb0 = sB0[col], bb1 = sB0[col + 1];
                sH[r0 * PZ + col    ] = tanh_fast(acc[nn][0] + bb0);
                sH[r0 * PZ + col + 1] = tanh_fast(acc[nn][1] + bb1);
                sH[r1 * PZ + col    ] = tanh_fast(acc[nn][2] + bb0);
                sH[r1 * PZ + col + 1] = tanh_fast(acc[nn][3] + bb1);
            }
        }
        __syncthreads();

        // ---- GEMM2: mu/sig heads, K=56 (7 ktiles), N=64 (4 ntiles/warp) ----
        {
            float am[4][4] = {};
            float as[4][4] = {};
#pragma unroll
            for (int kt = 0; kt < 7; kt++) {
                uint32_t ah[4], al[4];
                split_tf32(sH[r0 * PZ + tig +     8 * kt], ah[0], al[0]);
                split_tf32(sH[r1 * PZ + tig +     8 * kt], ah[1], al[1]);
                split_tf32(sH[r0 * PZ + tig + 4 + 8 * kt], ah[2], al[2]);
                split_tf32(sH[r1 * PZ + tig + 4 + 8 * kt], ah[3], al[3]);
#pragma unroll
                for (int nn = 0; nn < 4; nn++) {
                    int nrow = 8 * (wn * 4 + nn) + gid;
                    uint32_t bh0, bl0, bh1, bl1;
                    split_tf32(sW1[nrow * PZ + tig +     8 * kt], bh0, bl0);
                    split_tf32(sW1[nrow * PZ + tig + 4 + 8 * kt], bh1, bl1);
                    mma8(am[nn], ah, bh0, bh1);
                    mma8(am[nn], ah, bl0, bl1);
                    mma8(am[nn], al, bh0, bh1);
                    split_tf32(sW2[nrow * PZ + tig +     8 * kt], bh0, bl0);
                    split_tf32(sW2[nrow * PZ + tig + 4 + 8 * kt], bh1, bl1);
                    mma8(as[nn], ah, bh0, bh1);
                    mma8(as[nn], ah, bl0, bl1);
                    mma8(as[nn], al, bh0, bh1);
                }
            }
            // ---- epilogue: sig, z update, logdet ----
            const bool fin = (cc >= 2);
#pragma unroll
            for (int nn = 0; nn < 4; nn++) {
                int col = 8 * (wn * 4 + nn) + 2 * tig;
#pragma unroll
                for (int d = 0; d < 2; d++) {
                    float bm = sB1[col + d];
                    float bs = sB2[col + d];
                    // frag 0/1 -> row r0 ; frag 2/3 -> row r1
                    {
                        float mu = am[nn][d] + bm;
                        float x  = as[nn][d] + bs;
                        float sg = fmaf(tanh_fast(0.5f * x), 0.5f, 0.5f);
                        ldp0 += __logf(sg);
                        float zn = fmaf(sZu[r0 * PZ + col + d], sg, mu);
                        sZu[r0 * PZ + col + d] = zn;
                        if (fin) ssp0 = fmaf(zn, zn, ssp0);
                    }
                    {
                        float mu = am[nn][d + 2] + bm;
                        float x  = as[nn][d + 2] + bs;
                        float sg = fmaf(tanh_fast(0.5f * x), 0.5f, 0.5f);
                        ldp1 += __logf(sg);
                        float zn = fmaf(sZu[r1 * PZ + col + d], sg, mu);
                        sZu[r1 * PZ + col + d] = zn;
                        if (fin) ssp1 = fmaf(zn, zn, ssp1);
                    }
                }
            }
        }
        __syncthreads();
    }

    // ================= write z (coalesced float4) =================
#pragma unroll
    for (int i = 0; i < 8; i++) {
        int idx = tid + TPB * i;           // 0..2047
        int row = idx >> 5, q = idx & 31;
        float4 v = (q < 16)
            ? *(const float4*)&sZ1[row * PZ + 4 * q]
            : *(const float4*)&sZ2[row * PZ + 4 * (q - 16)];
        ((float4*)out)[(size_t)(rowBase + row) * 32 + q] = v;
    }

    // ================= densities =================
    ldp0 += __shfl_xor_sync(0xffffffffu, ldp0, 1);
    ldp0 += __shfl_xor_sync(0xffffffffu, ldp0, 2);
    ldp1 += __shfl_xor_sync(0xffffffffu, ldp1, 1);
    ldp1 += __shfl_xor_sync(0xffffffffu, ldp1, 2);
    ssp0 += __shfl_xor_sync(0xffffffffu, ssp0, 1);
    ssp0 += __shfl_xor_sync(0xffffffffu, ssp0, 2);
    ssp1 += __shfl_xor_sync(0xffffffffu, ssp1, 1);
    ssp1 += __shfl_xor_sync(0xffffffffu, ssp1, 2);
    if (tig == 0) {
        sLD[wn * 64 + r0] = ldp0;
        sLD[wn * 64 + r1] = ldp1;
        sSS[wn * 64 + r0] = ssp0;
        sSS[wn * 64 + r1] = ssp1;
    }
    __syncthreads();
    if (tid < 64) {
        float l = sLD[tid] + sLD[64 + tid];
        float s = sSS[tid] + sSS[64 + tid];
        size_t base = (size_t)Brows * ZZ;
        out[base + rowBase + tid]         = -0.5f * s;
        out[base + Brows + rowBase + tid] = sQ0[tid] - l;
    }
}

extern "C" void kernel_launch(void* const* d_in, const int* in_sizes, int n_in,
                              void* d_out, int out_size)
{
    const float* mean   = (const float*)d_in[0];
    const float* logvar = (const float*)d_in[1];
    const float* eps    = (const float*)d_in[2];
    const float* W_in   = (const float*)d_in[3];
    const float* b_in   = (const float*)d_in[4];
    const float* W_mu   = (const float*)d_in[5];
    const float* b_mu   = (const float*)d_in[6];
    const float* W_sig  = (const float*)d_in[7];
    const float* b_sig  = (const float*)d_in[8];
    float* out = (float*)d_out;

    int Brows = in_sizes[0] / ZZ;

    static int attr_set = 0;
    if (!attr_set) {
        cudaFuncSetAttribute(flow_kernel, cudaFuncAttributeMaxDynamicSharedMemorySize, SMEM_BYTES);
        attr_set = 1;
    }

    int grid = Brows / MR;
    flow_kernel<<<grid, TPB, SMEM_BYTES>>>(mean, logvar, eps,
                                           W_in, b_in, W_mu, b_mu, W_sig, b_sig,
                                           out, Brows);
}